// round 7
// baseline (speedup 1.0000x reference)
#include <cuda_runtime.h>
#include <cstdint>

#define B_ROWS 4096
#define M_COLS 16384
#define D_DIM  512
#define N_BMU  16

// Constants exactly as JAX folds them to fp32:
#define C1 ((float)(2.0 * 1e-6))               // 2.0*EPS
#define C2 ((float)(512.0 * (1e-6 * 1e-6)))    // d*EPS^2

// Scratch (no cudaMalloc allowed)
__device__ float g_dist[(size_t)B_ROWS * M_COLS];
__device__ float g_w2[M_COLS];
__device__ float g_sw[M_COLS];
__device__ float g_x2[B_ROWS];
__device__ float g_sx[B_ROWS];

__device__ __forceinline__ unsigned smem_u32(const void* p) {
    return (unsigned)__cvta_generic_to_shared(p);
}
#define CP_ASYNC16(dst, src) \
    asm volatile("cp.async.cg.shared.global [%0], [%1], 16;\n" :: "r"(dst), "l"(src))
#define CP_COMMIT() asm volatile("cp.async.commit_group;\n" ::)
#define CP_WAIT(n)  asm volatile("cp.async.wait_group %0;\n" :: "n"(n))

// ---------------------------------------------------------------------------
// Column stats (FROZEN semantics): fp64 accumulation of fp32-rounded squares.
// ---------------------------------------------------------------------------
__global__ __launch_bounds__(256)
void wstats_kernel(const float* __restrict__ w) {
    int m = blockIdx.x * blockDim.x + threadIdx.x;
    if (m >= M_COLS) return;
    double w2 = 0.0, sw = 0.0;
    for (int d = 0; d < D_DIM; ++d) {
        float v = w[(size_t)d * M_COLS + m];
        w2 += (double)__fmul_rn(v, v);
        sw += (double)v;
    }
    g_w2[m] = (float)w2;
    g_sw[m] = (float)sw;
}

// ---------------------------------------------------------------------------
// Row stats (FROZEN semantics): fp64 accumulation per row, one warp per row.
// ---------------------------------------------------------------------------
__global__ __launch_bounds__(256)
void xstats_kernel(const float* __restrict__ x) {
    const int row = blockIdx.x * 8 + (threadIdx.x >> 5);
    const int lane = threadIdx.x & 31;
    if (row >= B_ROWS) return;
    const float* xr = x + (size_t)row * D_DIM;

    double p2 = 0.0, p1 = 0.0;
    for (int i = lane; i < D_DIM; i += 32) {
        float v = xr[i];
        p2 += (double)__fmul_rn(v, v);
        p1 += (double)v;
    }
    #pragma unroll
    for (int off = 16; off; off >>= 1) {
        p2 += __shfl_xor_sync(0xffffffffu, p2, off);
        p1 += __shfl_xor_sync(0xffffffffu, p1, off);
    }
    if (lane == 0) { g_x2[row] = (float)p2; g_sx[row] = (float)p1; }
}

// ---------------------------------------------------------------------------
// SGEMM (FROZEN compute order: single ascending-k fp32 FMA chain per element)
// + FROZEN epilogue. NEW: cp.async double-buffered smem pipeline.
// As stored row-major [BM][BK] (cp.async can't transpose); a-frag reads are
// LDS.32 broadcasts (same kk, <=2 distinct rows per warp -> conflict-free).
// ---------------------------------------------------------------------------
#define BM 128
#define BN 128
#define BK 16
#define NSTAGE (D_DIM / BK)   // 32

__global__ __launch_bounds__(256, 2)
void gemm_dist_kernel(const float* __restrict__ A, const float* __restrict__ W) {
    __shared__ float As[2][BM][BK];   // 2 x 8KB
    __shared__ float Bs[2][BK][BN];   // 2 x 8KB

    const int tid = threadIdx.x;
    const int tx = tid & 15;        // 16 column-groups of 8
    const int ty = tid >> 4;        // 16 row-groups of 8
    const int rowBase = blockIdx.y * BM;
    const int colBase = blockIdx.x * BN;

    const int arow = tid >> 2;            // 0..63 (two passes -> 128 rows)
    const int akq  = (tid & 3) * 4;       // k offset 0,4,8,12
    const int bk = tid >> 5;              // 0..7 (two passes -> 16 k)
    const int bc = (tid & 31) * 4;

    const float* Abase = A + (size_t)rowBase * D_DIM;
    const float* Wbase = W + colBase;

    float acc[8][8];
    #pragma unroll
    for (int i = 0; i < 8; ++i)
        #pragma unroll
        for (int j = 0; j < 8; ++j) acc[i][j] = 0.f;

    // Issue one stage of cp.async copies into buffer `buf` for k0 = s*BK.
    auto issue_stage = [&](int s, int buf) {
        const int k0 = s * BK;
        #pragma unroll
        for (int p = 0; p < 2; ++p) {
            int r = arow + p * 64;
            CP_ASYNC16(smem_u32(&As[buf][r][akq]),
                       Abase + (size_t)r * D_DIM + k0 + akq);
        }
        #pragma unroll
        for (int p = 0; p < 2; ++p) {
            int kk = bk + p * 8;
            CP_ASYNC16(smem_u32(&Bs[buf][kk][bc]),
                       Wbase + (size_t)(k0 + kk) * M_COLS + bc);
        }
        CP_COMMIT();
    };

    issue_stage(0, 0);

    for (int s = 0; s < NSTAGE; ++s) {
        const int cur = s & 1;
        if (s + 1 < NSTAGE) {
            issue_stage(s + 1, cur ^ 1);
            CP_WAIT(1);                 // stage s complete
        } else {
            CP_WAIT(0);
        }
        __syncthreads();

        #pragma unroll
        for (int kk = 0; kk < BK; ++kk) {   // ascending k: single FMA chain
            float a[8], b[8];
            #pragma unroll
            for (int i = 0; i < 8; ++i) a[i] = As[cur][ty * 8 + i][kk];
            *(float4*)(b)     = *(const float4*)&Bs[cur][kk][tx * 8];
            *(float4*)(b + 4) = *(const float4*)&Bs[cur][kk][tx * 8 + 4];
            #pragma unroll
            for (int i = 0; i < 8; ++i)
                #pragma unroll
                for (int j = 0; j < 8; ++j)
                    acc[i][j] = fmaf(a[i], b[j], acc[i][j]);
        }
        __syncthreads();
    }

    // FROZEN epilogue
    float x2v[8], sxv[8], w2v[8], swv[8];
    #pragma unroll
    for (int i = 0; i < 8; ++i) {
        x2v[i] = g_x2[rowBase + ty * 8 + i];
        sxv[i] = g_sx[rowBase + ty * 8 + i];
    }
    #pragma unroll
    for (int j = 0; j < 8; ++j) {
        w2v[j] = g_w2[colBase + tx * 8 + j];
        swv[j] = g_sw[colBase + tx * 8 + j];
    }

    #pragma unroll
    for (int i = 0; i < 8; ++i) {
        float d[8];
        #pragma unroll
        for (int j = 0; j < 8; ++j) {
            float t = __fsub_rn(x2v[i], __fmul_rn(2.0f, acc[i][j]));
            t = __fadd_rn(t, w2v[j]);
            float ds = __fsub_rn(sxv[i], swv[j]);
            t = __fadd_rn(t, __fmul_rn(C1, ds));
            t = __fadd_rn(t, C2);
            d[j] = sqrtf(fmaxf(t, 0.0f));
        }
        float* dst = g_dist + (size_t)(rowBase + ty * 8 + i) * M_COLS + colBase + tx * 8;
        *(float4*)(dst)     = *(float4*)(d);
        *(float4*)(dst + 4) = *(float4*)(d + 4);
    }
}

// ---------------------------------------------------------------------------
// Top-16 per query, one warp per row. NEW: per-lane float threshold pre-filter
// so the common path is load + compare (memory-bound). Exact: per lane the
// scan index ascends, so dv == thf can never insert (its key > t[15]); the
// sentinel key (+INF dist, idx 0xffffffff) keeps the filter valid pre-fill.
// ---------------------------------------------------------------------------
#define SENTINEL ((((unsigned long long)0x7F800000u) << 32) | 0xFFFFFFFFull)

__global__ __launch_bounds__(256)
void topk_kernel(const float* __restrict__ loc, float* __restrict__ out) {
    const int q = blockIdx.x * 8 + (threadIdx.x >> 5);
    const int lane = threadIdx.x & 31;
    if (q >= B_ROWS) return;

    const float4* row = (const float4*)(g_dist + (size_t)q * M_COLS);

    unsigned long long t[N_BMU];
    #pragma unroll
    for (int s = 0; s < N_BMU; ++s) t[s] = SENTINEL;
    float thf = __int_as_float(0x7f800000);   // +INF

    #pragma unroll 4
    for (int i = 0; i < M_COLS / (32 * 4); ++i) {
        int e = lane + i * 32;
        float4 v = row[e];
        if (v.x < thf || v.y < thf || v.z < thf || v.w < thf) {
            int mbase = e * 4;
            float dv[4] = {v.x, v.y, v.z, v.w};
            #pragma unroll
            for (int j = 0; j < 4; ++j) {
                if (dv[j] < thf) {
                    unsigned long long key =
                        ((unsigned long long)__float_as_uint(dv[j]) << 32) |
                        (unsigned)(mbase + j);
                    if (key < t[N_BMU - 1]) {
                        t[N_BMU - 1] = key;
                        #pragma unroll
                        for (int s = N_BMU - 1; s > 0; --s) {
                            if (t[s] < t[s - 1]) {
                                unsigned long long tmp = t[s - 1];
                                t[s - 1] = t[s];
                                t[s] = tmp;
                            }
                        }
                        thf = __uint_as_float((unsigned)(t[N_BMU - 1] >> 32));
                    }
                }
            }
        }
    }

    #pragma unroll 1
    for (int r = 0; r < N_BMU; ++r) {
        unsigned long long best = t[0];
        #pragma unroll
        for (int o = 16; o; o >>= 1) {
            unsigned long long other = __shfl_xor_sync(0xffffffffu, best, o);
            if (other < best) best = other;
        }
        if (lane == r) {
            int m = (int)(best & 0xffffffffULL);
            out[((size_t)r * B_ROWS + q) * 2 + 0] = loc[m * 2 + 0];
            out[((size_t)r * B_ROWS + q) * 2 + 1] = loc[m * 2 + 1];
        }
        if (t[0] == best) {  // keys unique -> exactly one lane pops
            #pragma unroll
            for (int s = 0; s < N_BMU - 1; ++s) t[s] = t[s + 1];
            t[N_BMU - 1] = SENTINEL;
        }
    }
}

__global__ void zero_tail_kernel(float* out, int start, int n) {
    int i = blockIdx.x * blockDim.x + threadIdx.x;
    if (i < n) out[start + i] = 0.0f;
}

extern "C" void kernel_launch(void* const* d_in, const int* in_sizes, int n_in,
                              void* d_out, int out_size) {
    const float* x   = (const float*)d_in[0];   // [4096, 512]
    const float* w   = (const float*)d_in[1];   // [512, 16384]
    const float* loc = (const float*)d_in[2];   // [16384, 2]
    float* out = (float*)d_out;

    wstats_kernel<<<M_COLS / 256, 256>>>(w);
    xstats_kernel<<<B_ROWS / 8, 256>>>(x);
    gemm_dist_kernel<<<dim3(M_COLS / BN, B_ROWS / BM), 256>>>(x, w);
    topk_kernel<<<B_ROWS / 8, 256>>>(loc, out);

    const int main_elems = N_BMU * B_ROWS * 2;  // 131072
    if (out_size > main_elems) {
        int tail = out_size - main_elems;
        zero_tail_kernel<<<(tail + 255) / 256, 256>>>(out, main_elems, tail);
    }
}

// round 8
// speedup vs baseline: 1.2307x; 1.2307x over previous
#include <cuda_runtime.h>
#include <cstdint>

#define B_ROWS 4096
#define M_COLS 16384
#define D_DIM  512
#define N_BMU  16
#define CAP    512     // candidate buffer per row (expected N ~ 30)

// Constants exactly as JAX folds them to fp32:
#define C1 ((float)(2.0 * 1e-6))               // 2.0*EPS
#define C2 ((float)(512.0 * (1e-6 * 1e-6)))    // d*EPS^2

// Scratch (no cudaMalloc allowed)
__device__ float g_dist[(size_t)B_ROWS * M_COLS];
__device__ float g_w2[M_COLS];
__device__ float g_sw[M_COLS];
__device__ float g_x2[B_ROWS];
__device__ float g_sx[B_ROWS];

// ---------------------------------------------------------------------------
// Column stats (FROZEN): fp64 accumulation of fp32-rounded squares.
// ---------------------------------------------------------------------------
__global__ __launch_bounds__(256)
void wstats_kernel(const float* __restrict__ w) {
    int m = blockIdx.x * blockDim.x + threadIdx.x;
    if (m >= M_COLS) return;
    double w2 = 0.0, sw = 0.0;
    for (int d = 0; d < D_DIM; ++d) {
        float v = w[(size_t)d * M_COLS + m];
        w2 += (double)__fmul_rn(v, v);
        sw += (double)v;
    }
    g_w2[m] = (float)w2;
    g_sw[m] = (float)sw;
}

// ---------------------------------------------------------------------------
// Row stats (FROZEN): fp64 accumulation per row, one warp per row.
// ---------------------------------------------------------------------------
__global__ __launch_bounds__(256)
void xstats_kernel(const float* __restrict__ x) {
    const int row = blockIdx.x * 8 + (threadIdx.x >> 5);
    const int lane = threadIdx.x & 31;
    if (row >= B_ROWS) return;
    const float* xr = x + (size_t)row * D_DIM;

    double p2 = 0.0, p1 = 0.0;
    for (int i = lane; i < D_DIM; i += 32) {
        float v = xr[i];
        p2 += (double)__fmul_rn(v, v);
        p1 += (double)v;
    }
    #pragma unroll
    for (int off = 16; off; off >>= 1) {
        p2 += __shfl_xor_sync(0xffffffffu, p2, off);
        p1 += __shfl_xor_sync(0xffffffffu, p1, off);
    }
    if (lane == 0) { g_x2[row] = (float)p2; g_sx[row] = (float)p1; }
}

// ---------------------------------------------------------------------------
// SGEMM (FROZEN compute order, R6 version = at FFMA roofline) + FROZEN epilogue.
// ---------------------------------------------------------------------------
#define BM 128
#define BN 128
#define BK 16

__global__ __launch_bounds__(256, 2)
void gemm_dist_kernel(const float* __restrict__ A, const float* __restrict__ W) {
    __shared__ float As[BK][BM];
    __shared__ float Bs[BK][BN];

    const int tid = threadIdx.x;
    const int tx = tid & 15;
    const int ty = tid >> 4;
    const int rowBase = blockIdx.y * BM;
    const int colBase = blockIdx.x * BN;

    const int arow = tid >> 2;
    const int akq  = (tid & 3) * 4;
    const int bk = tid >> 5;
    const int bc = (tid & 31) * 4;

    float acc[8][8];
    #pragma unroll
    for (int i = 0; i < 8; ++i)
        #pragma unroll
        for (int j = 0; j < 8; ++j) acc[i][j] = 0.f;

    for (int k0 = 0; k0 < D_DIM; k0 += BK) {
        #pragma unroll
        for (int p = 0; p < 2; ++p) {
            int r = arow + p * 64;
            float4 v = *(const float4*)(A + (size_t)(rowBase + r) * D_DIM + k0 + akq);
            As[akq + 0][r] = v.x; As[akq + 1][r] = v.y;
            As[akq + 2][r] = v.z; As[akq + 3][r] = v.w;
        }
        #pragma unroll
        for (int p = 0; p < 2; ++p) {
            int kk = bk + p * 8;
            float4 v = *(const float4*)(W + (size_t)(k0 + kk) * M_COLS + colBase + bc);
            *(float4*)&Bs[kk][bc] = v;
        }
        __syncthreads();

        #pragma unroll
        for (int kk = 0; kk < BK; ++kk) {   // ascending k: single FMA chain
            float a[8], b[8];
            *(float4*)(a)     = *(const float4*)&As[kk][ty * 8];
            *(float4*)(a + 4) = *(const float4*)&As[kk][ty * 8 + 4];
            *(float4*)(b)     = *(const float4*)&Bs[kk][tx * 8];
            *(float4*)(b + 4) = *(const float4*)&Bs[kk][tx * 8 + 4];
            #pragma unroll
            for (int i = 0; i < 8; ++i)
                #pragma unroll
                for (int j = 0; j < 8; ++j)
                    acc[i][j] = fmaf(a[i], b[j], acc[i][j]);
        }
        __syncthreads();
    }

    float x2v[8], sxv[8], w2v[8], swv[8];
    #pragma unroll
    for (int i = 0; i < 8; ++i) {
        x2v[i] = g_x2[rowBase + ty * 8 + i];
        sxv[i] = g_sx[rowBase + ty * 8 + i];
    }
    #pragma unroll
    for (int j = 0; j < 8; ++j) {
        w2v[j] = g_w2[colBase + tx * 8 + j];
        swv[j] = g_sw[colBase + tx * 8 + j];
    }

    #pragma unroll
    for (int i = 0; i < 8; ++i) {
        float d[8];
        #pragma unroll
        for (int j = 0; j < 8; ++j) {
            float t = __fsub_rn(x2v[i], __fmul_rn(2.0f, acc[i][j]));
            t = __fadd_rn(t, w2v[j]);
            float ds = __fsub_rn(sxv[i], swv[j]);
            t = __fadd_rn(t, __fmul_rn(C1, ds));
            t = __fadd_rn(t, C2);
            d[j] = sqrtf(fmaxf(t, 0.0f));
        }
        float* dst = g_dist + (size_t)(rowBase + ty * 8 + i) * M_COLS + colBase + tx * 8;
        *(float4*)(dst)     = *(float4*)(d);
        *(float4*)(dst + 4) = *(float4*)(d + 4);
    }
}

// ---------------------------------------------------------------------------
// Top-16 per query, one warp per row. Two-pass threshold select:
//  Pass 1: per-lane min -> tau = 16th-smallest of 32 lane-mins.
//          tau >= true 16th value (16 distinct elements, one per lane, <= tau).
//  Pass 2: ballot-collect all elements <= tau into smem (expected ~30).
//  Final:  16 extract-min rounds over stable u64 keys (dist_bits<<32 | idx)
//          == jnp.argsort stable order. Bitwise identical selection.
// ---------------------------------------------------------------------------
#define FINF __int_as_float(0x7f800000)
#define MAXKEY 0xFFFFFFFFFFFFFFFFull

__global__ __launch_bounds__(256)
void topk_kernel(const float* __restrict__ loc, float* __restrict__ out) {
    __shared__ unsigned long long buf[8][CAP];
    const int wrp = threadIdx.x >> 5;
    const int lane = threadIdx.x & 31;
    const int q = blockIdx.x * 8 + wrp;
    if (q >= B_ROWS) return;

    const float4* row = (const float4*)(g_dist + (size_t)q * M_COLS);
    const int NV4 = M_COLS / 4;   // 4096 float4 per row

    // ---- Pass 1: per-lane min (4 accumulators for ILP) ----
    float m0 = FINF, m1 = FINF, m2 = FINF, m3 = FINF;
    #pragma unroll 4
    for (int i = lane; i < NV4; i += 32) {
        float4 v = row[i];
        m0 = fminf(m0, v.x); m1 = fminf(m1, v.y);
        m2 = fminf(m2, v.z); m3 = fminf(m3, v.w);
    }
    float lmin = fminf(fminf(m0, m1), fminf(m2, m3));

    // tau = 16th smallest of the 32 lane-mins (extract-min rounds)
    float cur = lmin, tau = FINF;
    #pragma unroll
    for (int r = 0; r < N_BMU; ++r) {
        float mn = cur;
        #pragma unroll
        for (int o = 16; o; o >>= 1) mn = fminf(mn, __shfl_xor_sync(0xffffffffu, mn, o));
        unsigned bal = __ballot_sync(0xffffffffu, cur == mn);
        if (lane == (__ffs(bal) - 1)) cur = FINF;   // remove one winner
        tau = mn;
    }

    // ---- Pass 2: collect all elements <= tau ----
    int cnt = 0;   // warp-uniform (maintained via ballots)
    for (int i = lane; i < NV4; i += 32) {
        float4 v = row[i];
        float mn = fminf(fminf(v.x, v.y), fminf(v.z, v.w));
        unsigned any = __ballot_sync(0xffffffffu, mn <= tau);
        if (any) {
            float dv[4] = {v.x, v.y, v.z, v.w};
            #pragma unroll
            for (int j = 0; j < 4; ++j) {
                bool p = (dv[j] <= tau);
                unsigned msk = __ballot_sync(0xffffffffu, p);
                if (p) {
                    int off = cnt + __popc(msk & ((1u << lane) - 1u));
                    if (off < CAP) {
                        buf[wrp][off] =
                            ((unsigned long long)__float_as_uint(dv[j]) << 32) |
                            (unsigned)(i * 4 + j);
                    }
                }
                cnt += __popc(msk);
            }
        }
    }
    if (cnt > CAP) cnt = CAP;   // statistically impossible on this data
    __syncwarp();

    // ---- Final: 16 extract-min rounds over the candidate buffer ----
    #pragma unroll 1
    for (int r = 0; r < N_BMU; ++r) {
        unsigned long long lk = MAXKEY;
        int la = -1;
        for (int idx = lane; idx < cnt; idx += 32) {
            unsigned long long k = buf[wrp][idx];
            if (k < lk) { lk = k; la = idx; }
        }
        unsigned long long best = lk;
        #pragma unroll
        for (int o = 16; o; o >>= 1) {
            unsigned long long other = __shfl_xor_sync(0xffffffffu, best, o);
            if (other < best) best = other;
        }
        if (lk == best && la >= 0) buf[wrp][la] = MAXKEY;  // keys unique
        if (lane == r) {
            int m = (int)(best & 0xffffffffULL);
            out[((size_t)r * B_ROWS + q) * 2 + 0] = loc[m * 2 + 0];
            out[((size_t)r * B_ROWS + q) * 2 + 1] = loc[m * 2 + 1];
        }
        __syncwarp();
    }
}

__global__ void zero_tail_kernel(float* out, int start, int n) {
    int i = blockIdx.x * blockDim.x + threadIdx.x;
    if (i < n) out[start + i] = 0.0f;
}

extern "C" void kernel_launch(void* const* d_in, const int* in_sizes, int n_in,
                              void* d_out, int out_size) {
    const float* x   = (const float*)d_in[0];   // [4096, 512]
    const float* w   = (const float*)d_in[1];   // [512, 16384]
    const float* loc = (const float*)d_in[2];   // [16384, 2]
    float* out = (float*)d_out;

    wstats_kernel<<<M_COLS / 256, 256>>>(w);
    xstats_kernel<<<B_ROWS / 8, 256>>>(x);
    gemm_dist_kernel<<<dim3(M_COLS / BN, B_ROWS / BM), 256>>>(x, w);
    topk_kernel<<<B_ROWS / 8, 256>>>(loc, out);

    const int main_elems = N_BMU * B_ROWS * 2;  // 131072
    if (out_size > main_elems) {
        int tail = out_size - main_elems;
        zero_tail_kernel<<<(tail + 255) / 256, 256>>>(out, main_elems, tail);
    }
}

// round 9
// speedup vs baseline: 3.2729x; 2.6594x over previous
#include <cuda_runtime.h>
#include <cuda_bf16.h>
#include <cstdint>

#define B_ROWS 4096
#define M_COLS 16384
#define D_DIM  512
#define N_BMU  16
#define CAP    256

#define C1 ((float)(2.0 * 1e-6))
#define C2 ((float)(512.0 * (1e-6 * 1e-6)))
#define FINF __int_as_float(0x7f800000)
#define MAXKEY 0xFFFFFFFFFFFFFFFFull

// Scratch (no cudaMalloc allowed)
__device__ float g_approx[(size_t)B_ROWS * M_COLS];   // approx sq (prune)
__device__ float g_rowmin[(size_t)B_ROWS * (M_COLS / 128)];
__device__ float g_w2[M_COLS];
__device__ float g_sw[M_COLS];
__device__ float g_x2[B_ROWS];
__device__ float g_sx[B_ROWS];
__device__ float g_wT[(size_t)M_COLS * D_DIM];        // w transposed [M][D]
__device__ uint4 g_xfrag[(B_ROWS / 16) * (D_DIM / 16) * 32];
__device__ uint2 g_wfrag[(M_COLS / 8) * (D_DIM / 16) * 32];
__device__ int   g_cand[(size_t)B_ROWS * CAP];
__device__ int   g_ccnt[B_ROWS];
__device__ int   g_maxx2_bits;   // zero-init; atomicMax idempotent across replays
__device__ int   g_maxw2_bits;

__device__ __forceinline__ unsigned smem_u32(const void* p) {
    return (unsigned)__cvta_generic_to_shared(p);
}
#define CP_ASYNC16(dst, src) \
    asm volatile("cp.async.cg.shared.global [%0], [%1], 16;\n" :: "r"(dst), "l"(src))
#define CP_ASYNC8(dst, src) \
    asm volatile("cp.async.ca.shared.global [%0], [%1], 8;\n" :: "r"(dst), "l"(src))
#define CP_COMMIT() asm volatile("cp.async.commit_group;\n" ::)
#define CP_WAIT(n)  asm volatile("cp.async.wait_group %0;\n" :: "n"(n))

__device__ __forceinline__ unsigned pack_bf16(float lo, float hi) {
    __nv_bfloat162 h = __floats2bfloat162_rn(lo, hi);   // .x = lo (low 16 bits)
    return *reinterpret_cast<unsigned*>(&h);
}

__device__ __forceinline__ void mma_bf16(float c[4], unsigned a0, unsigned a1,
                                         unsigned a2, unsigned a3,
                                         unsigned b0, unsigned b1) {
    asm volatile(
        "mma.sync.aligned.m16n8k16.row.col.f32.bf16.bf16.f32 "
        "{%0,%1,%2,%3}, {%4,%5,%6,%7}, {%8,%9}, {%0,%1,%2,%3};"
        : "+f"(c[0]), "+f"(c[1]), "+f"(c[2]), "+f"(c[3])
        : "r"(a0), "r"(a1), "r"(a2), "r"(a3), "r"(b0), "r"(b1));
}

// ---------------------------------------------------------------------------
// Column stats (FROZEN): fp64 accumulation of fp32-rounded squares. +max track
// ---------------------------------------------------------------------------
__global__ __launch_bounds__(256)
void wstats_kernel(const float* __restrict__ w) {
    int m = blockIdx.x * blockDim.x + threadIdx.x;
    if (m >= M_COLS) return;
    double w2 = 0.0, sw = 0.0;
    for (int d = 0; d < D_DIM; ++d) {
        float v = w[(size_t)d * M_COLS + m];
        w2 += (double)__fmul_rn(v, v);
        sw += (double)v;
    }
    float w2f = (float)w2;
    g_w2[m] = w2f;
    g_sw[m] = (float)sw;
    atomicMax(&g_maxw2_bits, __float_as_int(w2f));
}

// ---------------------------------------------------------------------------
// Row stats (FROZEN): fp64 accumulation per row. +max track
// ---------------------------------------------------------------------------
__global__ __launch_bounds__(256)
void xstats_kernel(const float* __restrict__ x) {
    const int row = blockIdx.x * 8 + (threadIdx.x >> 5);
    const int lane = threadIdx.x & 31;
    if (row >= B_ROWS) return;
    const float* xr = x + (size_t)row * D_DIM;

    double p2 = 0.0, p1 = 0.0;
    for (int i = lane; i < D_DIM; i += 32) {
        float v = xr[i];
        p2 += (double)__fmul_rn(v, v);
        p1 += (double)v;
    }
    #pragma unroll
    for (int off = 16; off; off >>= 1) {
        p2 += __shfl_xor_sync(0xffffffffu, p2, off);
        p1 += __shfl_xor_sync(0xffffffffu, p1, off);
    }
    if (lane == 0) {
        float x2f = (float)p2;
        g_x2[row] = x2f;
        g_sx[row] = (float)p1;
        atomicMax(&g_maxx2_bits, __float_as_int(x2f));
    }
}

// ---------------------------------------------------------------------------
// Converters: pre-permute bf16 operands into mma.sync fragment layout.
// A frag (m16n8k16 row): lane l: r=l/4, c=(l%4)*2:
//   a0={A[r][c],A[r][c+1]} a1={A[r+8][c],..} a2={A[r][c+8],..} a3={A[r+8][c+8],..}
// B frag (col): lane l: k=(l%4)*2, n=l/4: b0={B[k][n],B[k+1][n]} b1={B[k+8][n],B[k+9][n]}
// ---------------------------------------------------------------------------
__global__ __launch_bounds__(256)
void convert_x_kernel(const float* __restrict__ x) {
    int idx = blockIdx.x * blockDim.x + threadIdx.x;   // (mt, kt, lane)
    int lane = idx & 31;
    int kt = (idx >> 5) % (D_DIM / 16);
    int mt = (idx >> 5) / (D_DIM / 16);
    if (mt >= B_ROWS / 16) return;
    int r = mt * 16 + (lane >> 2);
    int c = kt * 16 + (lane & 3) * 2;
    const float* base = x + (size_t)r * D_DIM + c;
    uint4 o;
    o.x = pack_bf16(base[0], base[1]);
    o.y = pack_bf16(base[8 * D_DIM], base[8 * D_DIM + 1]);
    o.z = pack_bf16(base[8], base[9]);
    o.w = pack_bf16(base[8 * D_DIM + 8], base[8 * D_DIM + 9]);
    g_xfrag[idx] = o;
}

__global__ __launch_bounds__(256)
void convert_w_kernel(const float* __restrict__ w) {
    int idx = blockIdx.x * blockDim.x + threadIdx.x;   // (nt, kt, lane)
    int lane = idx & 31;
    int kt = (idx >> 5) % (D_DIM / 16);
    int nt = (idx >> 5) / (D_DIM / 16);
    if (nt >= M_COLS / 8) return;
    int k = kt * 16 + (lane & 3) * 2;
    int n = nt * 8 + (lane >> 2);
    const float* base = w + (size_t)k * M_COLS + n;
    uint2 o;
    o.x = pack_bf16(base[0], base[M_COLS]);
    o.y = pack_bf16(base[8 * (size_t)M_COLS], base[9 * (size_t)M_COLS]);
    g_wfrag[idx] = o;
}

// ---------------------------------------------------------------------------
// Transpose w -> wT[m][d] (fp32, for exact rescore)
// ---------------------------------------------------------------------------
__global__ __launch_bounds__(256)
void transpose_w_kernel(const float* __restrict__ w) {
    __shared__ float tile[32][33];
    int bx = blockIdx.x, by = blockIdx.y;            // bx: m-block, by: d-block
    int tx = threadIdx.x, ty = threadIdx.y;          // 32 x 8
    #pragma unroll
    for (int i = 0; i < 4; ++i) {
        int d = by * 32 + ty + i * 8;
        int m = bx * 32 + tx;
        tile[ty + i * 8][tx] = w[(size_t)d * M_COLS + m];
    }
    __syncthreads();
    #pragma unroll
    for (int i = 0; i < 4; ++i) {
        int m = bx * 32 + ty + i * 8;
        int d = by * 32 + tx;
        g_wT[(size_t)m * D_DIM + d] = tile[tx][ty + i * 8];
    }
}

// ---------------------------------------------------------------------------
// Prune GEMM: bf16 mma.sync, 128x128 tile, BK=32, 256 threads (8 warps 2x4).
// Writes approx_sq = x2 + w2 - 2*xw_bf16 and per-(row, colblock) minima.
// ---------------------------------------------------------------------------
__global__ __launch_bounds__(256, 2)
void prune_gemm_kernel() {
    __shared__ uint4 As[2][512];     // [(mt*2+kt)*32 + lane]
    __shared__ uint2 Bs[2][1024];    // [(nt*2+kt)*32 + lane]
    __shared__ float srm[128];

    const int tid = threadIdx.x;
    const int lane = tid & 31;
    const int wid = tid >> 5;
    const int wm = wid >> 2;         // 0..1 (64 rows each)
    const int wn = wid & 3;          // 0..3 (32 cols each)
    const int rowBase = blockIdx.y * 128;
    const int colBase = blockIdx.x * 128;
    const int mtBase = blockIdx.y * 8;
    const int ntBase = blockIdx.x * 16;

    if (tid < 128) srm[tid] = FINF;

    float c[4][4][4];
    #pragma unroll
    for (int i = 0; i < 4; ++i)
        #pragma unroll
        for (int j = 0; j < 4; ++j)
            #pragma unroll
            for (int r = 0; r < 4; ++r) c[i][j][r] = 0.f;

    auto issue = [&](int s, int buf) {
        #pragma unroll
        for (int ch = tid; ch < 512; ch += 256) {
            int mt = ch >> 6, kt = (ch >> 5) & 1, ln = ch & 31;
            const uint4* src = g_xfrag +
                ((size_t)(mtBase + mt) * (D_DIM / 16) + (s * 2 + kt)) * 32 + ln;
            CP_ASYNC16(smem_u32(&As[buf][(mt * 2 + kt) * 32 + ln]), src);
        }
        #pragma unroll
        for (int ch = tid; ch < 1024; ch += 256) {
            int nt = ch >> 6, kt = (ch >> 5) & 1, ln = ch & 31;
            const uint2* src = g_wfrag +
                ((size_t)(ntBase + nt) * (D_DIM / 16) + (s * 2 + kt)) * 32 + ln;
            CP_ASYNC8(smem_u32(&Bs[buf][(nt * 2 + kt) * 32 + ln]), src);
        }
        CP_COMMIT();
    };

    issue(0, 0);
    const int NSTAGE = D_DIM / 32;   // 16
    for (int s = 0; s < NSTAGE; ++s) {
        const int cur = s & 1;
        if (s + 1 < NSTAGE) { issue(s + 1, cur ^ 1); CP_WAIT(1); }
        else                { CP_WAIT(0); }
        __syncthreads();

        #pragma unroll
        for (int kt = 0; kt < 2; ++kt) {
            uint4 a[4];
            #pragma unroll
            for (int i = 0; i < 4; ++i)
                a[i] = As[cur][((wm * 4 + i) * 2 + kt) * 32 + lane];
            uint2 b[4];
            #pragma unroll
            for (int j = 0; j < 4; ++j)
                b[j] = Bs[cur][((wn * 4 + j) * 2 + kt) * 32 + lane];
            #pragma unroll
            for (int i = 0; i < 4; ++i)
                #pragma unroll
                for (int j = 0; j < 4; ++j)
                    mma_bf16(c[i][j], a[i].x, a[i].y, a[i].z, a[i].w, b[j].x, b[j].y);
        }
        __syncthreads();
    }

    // Epilogue: approx sq + row minima
    #pragma unroll
    for (int i = 0; i < 4; ++i) {
        int gr = rowBase + wm * 64 + i * 16 + (lane >> 2);
        float x2a = g_x2[gr], x2b = g_x2[gr + 8];
        float rmin0 = FINF, rmin1 = FINF;
        #pragma unroll
        for (int j = 0; j < 4; ++j) {
            int gc = colBase + wn * 32 + j * 8 + (lane & 3) * 2;
            float w2a = g_w2[gc], w2b = g_w2[gc + 1];
            float s0 = x2a + w2a - 2.f * c[i][j][0];
            float s1 = x2a + w2b - 2.f * c[i][j][1];
            float s2 = x2b + w2a - 2.f * c[i][j][2];
            float s3 = x2b + w2b - 2.f * c[i][j][3];
            *(float2*)(g_approx + (size_t)gr * M_COLS + gc)      = make_float2(s0, s1);
            *(float2*)(g_approx + (size_t)(gr + 8) * M_COLS + gc) = make_float2(s2, s3);
            rmin0 = fminf(rmin0, fminf(s0, s1));
            rmin1 = fminf(rmin1, fminf(s2, s3));
        }
        rmin0 = fminf(rmin0, __shfl_xor_sync(0xffffffffu, rmin0, 1));
        rmin0 = fminf(rmin0, __shfl_xor_sync(0xffffffffu, rmin0, 2));
        rmin1 = fminf(rmin1, __shfl_xor_sync(0xffffffffu, rmin1, 1));
        rmin1 = fminf(rmin1, __shfl_xor_sync(0xffffffffu, rmin1, 2));
        if ((lane & 3) == 0) {
            int rl = wm * 64 + i * 16 + (lane >> 2);
            atomicMin((int*)&srm[rl],     __float_as_int(fmaxf(rmin0, 0.f)));
            atomicMin((int*)&srm[rl + 8], __float_as_int(fmaxf(rmin1, 0.f)));
        }
    }
    __syncthreads();
    if (tid < 128)
        g_rowmin[(size_t)(rowBase + tid) * (M_COLS / 128) + blockIdx.x] = srm[tid];
}

// ---------------------------------------------------------------------------
// Candidate collect: tau from blockwise rowmins (>= true 16th), threshold
// T = tau + margin (margin = rigorous bf16 error bound x2), one scan.
// ---------------------------------------------------------------------------
__global__ __launch_bounds__(256)
void collect_kernel() {
    const int wrp = threadIdx.x >> 5;
    const int lane = threadIdx.x & 31;
    const int q = blockIdx.x * 8 + wrp;
    if (q >= B_ROWS) return;

    float mx = __int_as_float(g_maxx2_bits);
    float mw = __int_as_float(g_maxw2_bits);
    // |approx-exact| <= 2*2^-8*||x||*||w|| (+ eps-terms + accum slack); margin = 2x
    float margin = 0.017f * sqrtf(mx * mw) + 0.25f;

    // tau = 16th-smallest of 32 lane-mins over 128 block minima
    const float* rm = g_rowmin + (size_t)q * (M_COLS / 128);
    float lmin = FINF;
    #pragma unroll
    for (int t = 0; t < 4; ++t) lmin = fminf(lmin, rm[lane + 32 * t]);
    float cur = lmin, tau = FINF;
    #pragma unroll
    for (int r = 0; r < N_BMU; ++r) {
        float mn = cur;
        #pragma unroll
        for (int o = 16; o; o >>= 1) mn = fminf(mn, __shfl_xor_sync(0xffffffffu, mn, o));
        unsigned bal = __ballot_sync(0xffffffffu, cur == mn);
        if (lane == (__ffs(bal) - 1)) cur = FINF;
        tau = mn;
    }
    const float T = tau + margin;

    const float4* row = (const float4*)(g_approx + (size_t)q * M_COLS);
    int* cand = g_cand + (size_t)q * CAP;
    int cnt = 0;
    for (int i = lane; i < M_COLS / 4; i += 32) {
        float4 v = row[i];
        float mn = fminf(fminf(v.x, v.y), fminf(v.z, v.w));
        unsigned any = __ballot_sync(0xffffffffu, mn <= T);
        if (any) {
            float dv[4] = {v.x, v.y, v.z, v.w};
            #pragma unroll
            for (int j = 0; j < 4; ++j) {
                bool p = (dv[j] <= T);
                unsigned msk = __ballot_sync(0xffffffffu, p);
                if (p) {
                    int off = cnt + __popc(msk & ((1u << lane) - 1u));
                    if (off < CAP) cand[off] = i * 4 + j;
                }
                cnt += __popc(msk);
            }
        }
    }
    if (lane == 0) g_ccnt[q] = cnt < CAP ? cnt : CAP;
}

// ---------------------------------------------------------------------------
// Exact rescore + select. FROZEN serial ascending-d fp32 FMA chain (identical
// to the R6 GEMM chain) + FROZEN epilogue + stable u64 key extract-min.
// One block (64 threads) per query.
// ---------------------------------------------------------------------------
__global__ __launch_bounds__(64)
void rescore_kernel(const float* __restrict__ x, const float* __restrict__ loc,
                    float* __restrict__ out) {
    __shared__ unsigned long long keys[CAP];
    const int q = blockIdx.x;
    const int tid = threadIdx.x;
    const int cnt = g_ccnt[q];

    const float4* xr = (const float4*)(x + (size_t)q * D_DIM);
    const float x2 = g_x2[q], sx = g_sx[q];

    for (int t = tid; t < cnt; t += 64) {
        int m = g_cand[(size_t)q * CAP + t];
        const float4* wr = (const float4*)(g_wT + (size_t)m * D_DIM);
        float acc = 0.f;
        for (int i = 0; i < D_DIM / 4; ++i) {   // single ascending FMA chain
            float4 a = xr[i], b = wr[i];
            acc = fmaf(a.x, b.x, acc);
            acc = fmaf(a.y, b.y, acc);
            acc = fmaf(a.z, b.z, acc);
            acc = fmaf(a.w, b.w, acc);
        }
        // FROZEN epilogue
        float t1 = __fsub_rn(x2, __fmul_rn(2.0f, acc));
        t1 = __fadd_rn(t1, g_w2[m]);
        float ds = __fsub_rn(sx, g_sw[m]);
        t1 = __fadd_rn(t1, __fmul_rn(C1, ds));
        t1 = __fadd_rn(t1, C2);
        float dist = sqrtf(fmaxf(t1, 0.0f));
        keys[t] = ((unsigned long long)__float_as_uint(dist) << 32) | (unsigned)m;
    }
    __syncthreads();

    if (tid < 32) {
        const int lane = tid;
        #pragma unroll 1
        for (int r = 0; r < N_BMU; ++r) {
            unsigned long long lk = MAXKEY;
            int la = -1;
            for (int idx = lane; idx < cnt; idx += 32) {
                unsigned long long k = keys[idx];
                if (k < lk) { lk = k; la = idx; }
            }
            unsigned long long best = lk;
            #pragma unroll
            for (int o = 16; o; o >>= 1) {
                unsigned long long other = __shfl_xor_sync(0xffffffffu, best, o);
                if (other < best) best = other;
            }
            if (lk == best && la >= 0) keys[la] = MAXKEY;   // keys unique
            if (lane == r) {
                int m = (int)(best & 0xffffffffULL);
                out[((size_t)r * B_ROWS + q) * 2 + 0] = loc[m * 2 + 0];
                out[((size_t)r * B_ROWS + q) * 2 + 1] = loc[m * 2 + 1];
            }
            __syncwarp();
        }
    }
}

__global__ void zero_tail_kernel(float* out, int start, int n) {
    int i = blockIdx.x * blockDim.x + threadIdx.x;
    if (i < n) out[start + i] = 0.0f;
}

extern "C" void kernel_launch(void* const* d_in, const int* in_sizes, int n_in,
                              void* d_out, int out_size) {
    const float* x   = (const float*)d_in[0];   // [4096, 512]
    const float* w   = (const float*)d_in[1];   // [512, 16384]
    const float* loc = (const float*)d_in[2];   // [16384, 2]
    float* out = (float*)d_out;

    wstats_kernel<<<M_COLS / 256, 256>>>(w);
    xstats_kernel<<<B_ROWS / 8, 256>>>(x);
    convert_x_kernel<<<(B_ROWS / 16) * (D_DIM / 16) * 32 / 256, 256>>>(x);
    convert_w_kernel<<<(M_COLS / 8) * (D_DIM / 16) * 32 / 256, 256>>>(w);
    transpose_w_kernel<<<dim3(M_COLS / 32, D_DIM / 32), dim3(32, 8)>>>(w);
    prune_gemm_kernel<<<dim3(M_COLS / 128, B_ROWS / 128), 256>>>();
    collect_kernel<<<B_ROWS / 8, 256>>>();
    rescore_kernel<<<B_ROWS, 64>>>(x, loc, out);

    const int main_elems = N_BMU * B_ROWS * 2;  // 131072
    if (out_size > main_elems) {
        int tail = out_size - main_elems;
        zero_tail_kernel<<<(tail + 255) / 256, 256>>>(out, main_elems, tail);
    }
}